// round 1
// baseline (speedup 1.0000x reference)
#include <cuda_runtime.h>

#define T49   49
#define TPAD  56
#define CDIM  128
#define NH    4
#define HDIM  32
#define NWIN  64

#define XP    132          // x_s / out2 pitch (floats)
#define QP    390          // qkv pitch (floats)
#define WSP   129          // staged-W pitch (float2 units)
#define AP    56           // attn pitch (floats)

#define OFF_X    0
#define OFF_W    (TPAD*XP)                 /* 7392  : W stage | attn     */
#define OFF_QKV  (OFF_W + 2*64*WSP)        /* 23904 : qkv               */
#define SMEM_FLOATS (OFF_QKV + TPAD*QP)    /* 45744                     */
#define SMEM_BYTES  (SMEM_FLOATS*4)        /* 182976                    */

typedef unsigned long long u64;

// packed fp32x2 FMA (Blackwell): d.lo += a.lo*b.lo ; d.hi += a.hi*b.hi
__device__ __forceinline__ void ffma2(u64 &d, u64 a, u64 b){
  asm("fma.rn.f32x2 %0, %1, %2, %0;" : "+l"(d) : "l"(a), "l"(b));
}
__device__ __forceinline__ u64 splat2(float x){
  u64 r; asm("mov.b64 %0, {%1, %1};" : "=l"(r) : "f"(x)); return r;
}
__device__ __forceinline__ float lohi(u64 v){
  float lo, hi; asm("mov.b64 {%0, %1}, %2;" : "=f"(lo), "=f"(hi) : "l"(v));
  return lo + hi;
}
__device__ __forceinline__ u64 lds64(const float* p){
  return *reinterpret_cast<const u64*>(p);
}

__global__ void __launch_bounds__(256, 1)
wattn_kernel(const float* __restrict__ x, const float* __restrict__ mask,
             const float* __restrict__ qkv_w, const float* __restrict__ qkv_b,
             const float* __restrict__ proj_w, const float* __restrict__ proj_b,
             const float* __restrict__ bias_table, float* __restrict__ out)
{
  extern __shared__ float sm[];
  float*  x_s  = sm + OFF_X;    // stage 1/2
  float*  o2   = sm + OFF_X;    // reuse: attn@V result (stage 3b/4)
  float*  w_s  = sm + OFF_W;    // staged weights (stage 2/4)
  float*  attn = sm + OFF_W;    // reuse: attention logits (stage 3)
  float*  qkv  = sm + OFF_QKV;
  float2* wk2  = reinterpret_cast<float2*>(w_s);

  const int b   = blockIdx.x;
  const int tid = threadIdx.x;
  const int tx  = tid & 31;          // lane: cols
  const int r0  = (tid >> 5) * 7;    // warp: 7-row group (rows 0..55)

  // ---------------- stage 1: load x tile (49x128, pad rows to 56 with 0) ----
  {
    const float4* xg = reinterpret_cast<const float4*>(x + (size_t)b*(T49*CDIM));
    #pragma unroll
    for (int it = 0; it < 7; ++it) {
      int i4 = tid + it*256;
      if (i4 < T49*CDIM/4) {
        float4 v = __ldg(xg + i4);
        *reinterpret_cast<float4*>(&x_s[(i4 >> 5)*XP + (i4 & 31)*4]) = v;
      }
    }
    if (tid < (TPAD-T49)*32) {
      *reinterpret_cast<float4*>(&x_s[(T49 + (tid >> 5))*XP + (tid & 31)*4]) =
          make_float4(0.f, 0.f, 0.f, 0.f);
    }
  }
  __syncthreads();

  // ---------------- stage 2: QKV = x @ qkv_w^T + qkv_b, 3 chunks of 128 ----
  for (int ch = 0; ch < 3; ++ch) {
    const float* wg = qkv_w + ch*CDIM*CDIM;
    #pragma unroll
    for (int it = 0; it < 32; ++it) {      // stage W chunk as k-pair-major
      int i  = tid + it*256;
      int c  = i >> 6, k2 = i & 63;
      wk2[k2*WSP + c] = __ldg(reinterpret_cast<const float2*>(wg + c*CDIM) + k2);
    }
    __syncthreads();

    u64 acc[7][4];
    #pragma unroll
    for (int i = 0; i < 7; ++i)
      #pragma unroll
      for (int j = 0; j < 4; ++j) acc[i][j] = 0ull;

    #pragma unroll 4
    for (int k2 = 0; k2 < 64; ++k2) {
      u64 bb[4], aa[7];
      #pragma unroll
      for (int j = 0; j < 4; ++j)          // lane-consecutive, conflict-free
        bb[j] = lds64(reinterpret_cast<const float*>(&wk2[k2*WSP + tx + 32*j]));
      #pragma unroll
      for (int i = 0; i < 7; ++i)          // warp-broadcast
        aa[i] = lds64(&x_s[(r0+i)*XP + 2*k2]);
      #pragma unroll
      for (int i = 0; i < 7; ++i)
        #pragma unroll
        for (int j = 0; j < 4; ++j)
          ffma2(acc[i][j], aa[i], bb[j]);
    }

    #pragma unroll
    for (int i = 0; i < 7; ++i) {
      int r = r0 + i;
      #pragma unroll
      for (int j = 0; j < 4; ++j) {
        int cc = ch*CDIM + tx + 32*j;
        qkv[r*QP + cc] = (r < T49) ? (lohi(acc[i][j]) + __ldg(&qkv_b[cc])) : 0.f;
      }
    }
    __syncthreads();
  }

  // ---------------- stage 3a: attn[h][t][s] = scale*q.k + bias + mask ------
  {
    const float scale = 0.17677669529663687f;   // 32^-0.5
    const float* mrow = mask + (size_t)(b & (NWIN-1))*(T49*T49);
    const int s1 = (tx + 32 < TPAD) ? (tx + 32) : 0;   // clamp (store guarded)
    #pragma unroll 1
    for (int h = 0; h < NH; ++h) {
      const int qo = h*HDIM, ko = CDIM + h*HDIM;
      u64 acc[7][2];
      #pragma unroll
      for (int i = 0; i < 7; ++i) { acc[i][0] = 0ull; acc[i][1] = 0ull; }
      #pragma unroll 4
      for (int d2 = 0; d2 < 16; ++d2) {
        u64 b0 = lds64(&qkv[tx*QP + ko + 2*d2]);
        u64 b1 = lds64(&qkv[s1*QP + ko + 2*d2]);
        #pragma unroll
        for (int i = 0; i < 7; ++i) {
          u64 aa = lds64(&qkv[(r0+i)*QP + qo + 2*d2]);
          ffma2(acc[i][0], aa, b0);
          ffma2(acc[i][1], aa, b1);
        }
      }
      #pragma unroll
      for (int i = 0; i < 7; ++i) {
        int t = r0 + i;
        int th = t / 7, tw = t - th*7;
        #pragma unroll
        for (int j = 0; j < 2; ++j) {
          int s = tx + 32*j;
          if (s < TPAD) {
            float v = lohi(acc[i][j]) * scale;
            if (t < T49 && s < T49) {
              int sh  = s / 7, sw = s - sh*7;
              int rel = (th - sh + 6)*13 + (tw - sw + 6);
              v += __ldg(&bias_table[rel*NH + h]) + __ldg(&mrow[t*T49 + s]);
            }
            attn[(h*TPAD + t)*AP + s] = v;
          }
        }
      }
    }
  }
  __syncthreads();

  // ---------------- stage 3b: out2 = attn @ v ------------------------------
  {
    const int cp0 = tx, cp1 = tx + 32;       // column pairs: c = 2*cp
    const int h0 = cp0 >> 4, h1 = cp1 >> 4;  // head = c/32 = cp/16
    u64 acc[7][2];
    #pragma unroll
    for (int i = 0; i < 7; ++i) { acc[i][0] = 0ull; acc[i][1] = 0ull; }
    #pragma unroll 2
    for (int s = 0; s < TPAD; ++s) {         // v rows >=49 are zero: safe
      u64 b0 = lds64(&qkv[s*QP + 2*CDIM + 2*cp0]);
      u64 b1 = lds64(&qkv[s*QP + 2*CDIM + 2*cp1]);
      #pragma unroll
      for (int i = 0; i < 7; ++i) {
        int t = r0 + i;
        ffma2(acc[i][0], splat2(attn[(h0*TPAD + t)*AP + s]), b0);
        ffma2(acc[i][1], splat2(attn[(h1*TPAD + t)*AP + s]), b1);
      }
    }
    #pragma unroll
    for (int i = 0; i < 7; ++i) {            // o2 region (x_s) long dead
      int t = r0 + i;
      *reinterpret_cast<u64*>(&o2[t*XP + 2*cp0]) = acc[i][0];
      *reinterpret_cast<u64*>(&o2[t*XP + 2*cp1]) = acc[i][1];
    }
  }
  __syncthreads();

  // ---------------- stage 4: out = o2 @ proj_w^T + proj_b ------------------
  {
    #pragma unroll
    for (int it = 0; it < 32; ++it) {        // attn region free now
      int i  = tid + it*256;
      int c  = i >> 6, k2 = i & 63;
      wk2[k2*WSP + c] = __ldg(reinterpret_cast<const float2*>(proj_w + c*CDIM) + k2);
    }
    __syncthreads();

    u64 acc[7][4];
    #pragma unroll
    for (int i = 0; i < 7; ++i)
      #pragma unroll
      for (int j = 0; j < 4; ++j) acc[i][j] = 0ull;

    #pragma unroll 4
    for (int k2 = 0; k2 < 64; ++k2) {
      u64 bb[4], aa[7];
      #pragma unroll
      for (int j = 0; j < 4; ++j)
        bb[j] = lds64(reinterpret_cast<const float*>(&wk2[k2*WSP + tx + 32*j]));
      #pragma unroll
      for (int i = 0; i < 7; ++i)
        aa[i] = lds64(&o2[(r0+i)*XP + 2*k2]);
      #pragma unroll
      for (int i = 0; i < 7; ++i)
        #pragma unroll
        for (int j = 0; j < 4; ++j)
          ffma2(acc[i][j], aa[i], bb[j]);
    }

    float* og = out + (size_t)b*(T49*CDIM);
    #pragma unroll
    for (int i = 0; i < 7; ++i) {
      int r = r0 + i;
      if (r < T49) {
        #pragma unroll
        for (int j = 0; j < 4; ++j) {
          int c = tx + 32*j;                 // lane-consecutive: coalesced
          og[r*CDIM + c] = lohi(acc[i][j]) + __ldg(&proj_b[c]);
        }
      }
    }
  }
}

extern "C" void kernel_launch(void* const* d_in, const int* in_sizes, int n_in,
                              void* d_out, int out_size)
{
  const float* x      = (const float*)d_in[0];
  const float* mask   = (const float*)d_in[1];
  const float* qkv_w  = (const float*)d_in[2];
  const float* qkv_b  = (const float*)d_in[3];
  const float* proj_w = (const float*)d_in[4];
  const float* proj_b = (const float*)d_in[5];
  const float* btab   = (const float*)d_in[6];
  float* out = (float*)d_out;

  int B = in_sizes[0] / (T49*CDIM);   // 8192 windows

  cudaFuncSetAttribute(wattn_kernel,
                       cudaFuncAttributeMaxDynamicSharedMemorySize, SMEM_BYTES);
  wattn_kernel<<<B, 256, SMEM_BYTES>>>(x, mask, qkv_w, qkv_b,
                                       proj_w, proj_b, btab, out);
}

// round 3
// speedup vs baseline: 1.0061x; 1.0061x over previous
#include <cuda_runtime.h>

#define T49   49
#define TPAD  56
#define CDIM  128
#define NH    4
#define HDIM  32
#define NWIN  64

#define XP    132          // x_s / out2 pitch (floats)
#define QP    390          // qkv pitch (floats)
#define WSP   129          // staged-W pitch (float2 units)
#define AP    56           // attn pitch (floats)

#define OFF_X    0
#define OFF_W    (TPAD*XP)                 /* 7392  : W stage | attn     */
#define OFF_QKV  (OFF_W + 2*64*WSP)        /* 23904 : qkv               */
#define SMEM_FLOATS (OFF_QKV + TPAD*QP)    /* 45744                     */
#define SMEM_BYTES  (SMEM_FLOATS*4)        /* 182976                    */

typedef unsigned long long u64;

// packed fp32x2 FMA (Blackwell): d.lo += a.lo*b.lo ; d.hi += a.hi*b.hi
__device__ __forceinline__ void ffma2(u64 &d, u64 a, u64 b){
  asm("fma.rn.f32x2 %0, %1, %2, %0;" : "+l"(d) : "l"(a), "l"(b));
}
__device__ __forceinline__ u64 splat2(float x){
  u64 r; asm("mov.b64 %0, {%1, %1};" : "=l"(r) : "f"(x)); return r;
}
__device__ __forceinline__ float lohi(u64 v){
  float lo, hi; asm("mov.b64 {%0, %1}, %2;" : "=f"(lo), "=f"(hi) : "l"(v));
  return lo + hi;
}
__device__ __forceinline__ u64 lds64(const float* p){
  return *reinterpret_cast<const u64*>(p);
}

__global__ void __launch_bounds__(256, 1)
wattn_kernel(const float* __restrict__ x, const float* __restrict__ mask,
             const float* __restrict__ qkv_w, const float* __restrict__ qkv_b,
             const float* __restrict__ proj_w, const float* __restrict__ proj_b,
             const float* __restrict__ bias_table, float* __restrict__ out)
{
  extern __shared__ float sm[];
  float*  x_s  = sm + OFF_X;    // stage 1/2
  float*  o2   = sm + OFF_X;    // reuse: attn@V result (stage 3b/4)
  float*  w_s  = sm + OFF_W;    // staged weights (stage 2/4)
  float*  attn = sm + OFF_W;    // reuse: attention logits (stage 3)
  float*  qkv  = sm + OFF_QKV;
  float2* wk2  = reinterpret_cast<float2*>(w_s);

  const int b   = blockIdx.x;
  const int tid = threadIdx.x;
  const int tx  = tid & 31;          // lane: cols
  const int r0  = (tid >> 5) * 7;    // warp: 7-row group (rows 0..55)

  // ---------------- stage 1: load x tile (49x128, pad rows to 56 with 0) ----
  {
    const float4* xg = reinterpret_cast<const float4*>(x + (size_t)b*(T49*CDIM));
    #pragma unroll
    for (int it = 0; it < 7; ++it) {
      int i4 = tid + it*256;
      if (i4 < T49*CDIM/4) {
        float4 v = __ldg(xg + i4);
        *reinterpret_cast<float4*>(&x_s[(i4 >> 5)*XP + (i4 & 31)*4]) = v;
      }
    }
    if (tid < (TPAD-T49)*32) {
      *reinterpret_cast<float4*>(&x_s[(T49 + (tid >> 5))*XP + (tid & 31)*4]) =
          make_float4(0.f, 0.f, 0.f, 0.f);
    }
  }
  __syncthreads();

  // ---------------- stage 2: QKV = x @ qkv_w^T + qkv_b, 3 chunks of 128 ----
  for (int ch = 0; ch < 3; ++ch) {
    const float* wg = qkv_w + ch*CDIM*CDIM;
    #pragma unroll
    for (int it = 0; it < 32; ++it) {      // stage W chunk as k-pair-major
      int i  = tid + it*256;
      int c  = i >> 6, k2 = i & 63;
      wk2[k2*WSP + c] = __ldg(reinterpret_cast<const float2*>(wg + c*CDIM) + k2);
    }
    __syncthreads();

    u64 acc[7][4];
    #pragma unroll
    for (int i = 0; i < 7; ++i)
      #pragma unroll
      for (int j = 0; j < 4; ++j) acc[i][j] = 0ull;

    #pragma unroll 4
    for (int k2 = 0; k2 < 64; ++k2) {
      u64 bb[4], aa[7];
      #pragma unroll
      for (int j = 0; j < 4; ++j)          // lane-consecutive, conflict-free
        bb[j] = lds64(reinterpret_cast<const float*>(&wk2[k2*WSP + tx + 32*j]));
      #pragma unroll
      for (int i = 0; i < 7; ++i)          // warp-broadcast
        aa[i] = lds64(&x_s[(r0+i)*XP + 2*k2]);
      #pragma unroll
      for (int i = 0; i < 7; ++i)
        #pragma unroll
        for (int j = 0; j < 4; ++j)
          ffma2(acc[i][j], aa[i], bb[j]);
    }

    #pragma unroll
    for (int i = 0; i < 7; ++i) {
      int r = r0 + i;
      #pragma unroll
      for (int j = 0; j < 4; ++j) {
        int cc = ch*CDIM + tx + 32*j;
        qkv[r*QP + cc] = (r < T49) ? (lohi(acc[i][j]) + __ldg(&qkv_b[cc])) : 0.f;
      }
    }
    __syncthreads();
  }

  // ---------------- stage 3a: attn[h][t][s] = scale*q.k + bias + mask ------
  {
    const float scale = 0.17677669529663687f;   // 32^-0.5
    const float* mrow = mask + (size_t)(b & (NWIN-1))*(T49*T49);
    const int s1 = (tx + 32 < TPAD) ? (tx + 32) : 0;   // clamp (store guarded)
    #pragma unroll 1
    for (int h = 0; h < NH; ++h) {
      const int qo = h*HDIM, ko = CDIM + h*HDIM;
      u64 acc[7][2];
      #pragma unroll
      for (int i = 0; i < 7; ++i) { acc[i][0] = 0ull; acc[i][1] = 0ull; }
      #pragma unroll 4
      for (int d2 = 0; d2 < 16; ++d2) {
        u64 b0 = lds64(&qkv[tx*QP + ko + 2*d2]);
        u64 b1 = lds64(&qkv[s1*QP + ko + 2*d2]);
        #pragma unroll
        for (int i = 0; i < 7; ++i) {
          u64 aa = lds64(&qkv[(r0+i)*QP + qo + 2*d2]);
          ffma2(acc[i][0], aa, b0);
          ffma2(acc[i][1], aa, b1);
        }
      }
      #pragma unroll
      for (int i = 0; i < 7; ++i) {
        int t = r0 + i;
        int th = t / 7, tw = t - th*7;
        #pragma unroll
        for (int j = 0; j < 2; ++j) {
          int s = tx + 32*j;
          if (s < TPAD) {
            float v = lohi(acc[i][j]) * scale;
            if (t < T49 && s < T49) {
              int sh  = s / 7, sw = s - sh*7;
              int rel = (th - sh + 6)*13 + (tw - sw + 6);
              v += __ldg(&bias_table[rel*NH + h]) + __ldg(&mrow[t*T49 + s]);
            }
            attn[(h*TPAD + t)*AP + s] = v;
          }
        }
      }
    }
  }
  __syncthreads();

  // ---------------- stage 3b: out2 = attn @ v ------------------------------
  {
    const int cp0 = tx, cp1 = tx + 32;       // column pairs: c = 2*cp
    const int h0 = cp0 >> 4, h1 = cp1 >> 4;  // head = c/32 = cp/16
    u64 acc[7][2];
    #pragma unroll
    for (int i = 0; i < 7; ++i) { acc[i][0] = 0ull; acc[i][1] = 0ull; }
    #pragma unroll 2
    for (int s = 0; s < TPAD; ++s) {         // v rows >=49 are zero: safe
      u64 b0 = lds64(&qkv[s*QP + 2*CDIM + 2*cp0]);
      u64 b1 = lds64(&qkv[s*QP + 2*CDIM + 2*cp1]);
      #pragma unroll
      for (int i = 0; i < 7; ++i) {
        int t = r0 + i;
        ffma2(acc[i][0], splat2(attn[(h0*TPAD + t)*AP + s]), b0);
        ffma2(acc[i][1], splat2(attn[(h1*TPAD + t)*AP + s]), b1);
      }
    }
    #pragma unroll
    for (int i = 0; i < 7; ++i) {            // o2 region (x_s) long dead
      int t = r0 + i;
      *reinterpret_cast<u64*>(&o2[t*XP + 2*cp0]) = acc[i][0];
      *reinterpret_cast<u64*>(&o2[t*XP + 2*cp1]) = acc[i][1];
    }
  }
  __syncthreads();

  // ---------------- stage 4: out = o2 @ proj_w^T + proj_b ------------------
  {
    #pragma unroll
    for (int it = 0; it < 32; ++it) {        // attn region free now
      int i  = tid + it*256;
      int c  = i >> 6, k2 = i & 63;
      wk2[k2*WSP + c] = __ldg(reinterpret_cast<const float2*>(proj_w + c*CDIM) + k2);
    }
    __syncthreads();

    u64 acc[7][4];
    #pragma unroll
    for (int i = 0; i < 7; ++i)
      #pragma unroll
      for (int j = 0; j < 4; ++j) acc[i][j] = 0ull;

    #pragma unroll 4
    for (int k2 = 0; k2 < 64; ++k2) {
      u64 bb[4], aa[7];
      #pragma unroll
      for (int j = 0; j < 4; ++j)
        bb[j] = lds64(reinterpret_cast<const float*>(&wk2[k2*WSP + tx + 32*j]));
      #pragma unroll
      for (int i = 0; i < 7; ++i)
        aa[i] = lds64(&o2[(r0+i)*XP + 2*k2]);
      #pragma unroll
      for (int i = 0; i < 7; ++i)
        #pragma unroll
        for (int j = 0; j < 4; ++j)
          ffma2(acc[i][j], aa[i], bb[j]);
    }

    float* og = out + (size_t)b*(T49*CDIM);
    #pragma unroll
    for (int i = 0; i < 7; ++i) {
      int r = r0 + i;
      if (r < T49) {
        #pragma unroll
        for (int j = 0; j < 4; ++j) {
          int c = tx + 32*j;                 // lane-consecutive: coalesced
          og[r*CDIM + c] = lohi(acc[i][j]) + __ldg(&proj_b[c]);
        }
      }
    }
  }
}

extern "C" void kernel_launch(void* const* d_in, const int* in_sizes, int n_in,
                              void* d_out, int out_size)
{
  const float* x      = (const float*)d_in[0];
  const float* mask   = (const float*)d_in[1];
  const float* qkv_w  = (const float*)d_in[2];
  const float* qkv_b  = (const float*)d_in[3];
  const float* proj_w = (const float*)d_in[4];
  const float* proj_b = (const float*)d_in[5];
  const float* btab   = (const float*)d_in[6];
  float* out = (float*)d_out;

  int B = in_sizes[0] / (T49*CDIM);   // 8192 windows

  cudaFuncSetAttribute(wattn_kernel,
                       cudaFuncAttributeMaxDynamicSharedMemorySize, SMEM_BYTES);
  wattn_kernel<<<B, 256, SMEM_BYTES>>>(x, mask, qkv_w, qkv_b,
                                       proj_w, proj_b, btab, out);
}